// round 7
// baseline (speedup 1.0000x reference)
#include <cuda_runtime.h>
#include <math.h>

#define S_TOK 32
#define H_DIM 768
#define I_DIM 768
#define E_NUM 32
#define K_TOP 4
#define TWO_I 1536
#define LIMIT 7.0f
#define ALPHA 1.702f
#define EPS 1e-5f
#define TMAX 8   // tokens resident in SMEM per pass (zero-padded to mult of 4)

// -------- device scratch --------
__device__ float g_t[S_TOK][H_DIM];
__device__ int   g_topk_idx[S_TOK][K_TOP];
__device__ float g_topk_w[S_TOK][K_TOP];
__device__ int   g_cnt[E_NUM];
__device__ int   g_tok[E_NUM][S_TOK];
__device__ float g_ew[E_NUM][S_TOK];
__device__ float g_act[E_NUM][S_TOK][I_DIM];

// ======================================================================
// Kernel 1: RMSNorm + residual init + router logits + top-4 + softmax
// ======================================================================
__global__ void __launch_bounds__(256) k_route(
    const float* __restrict__ x, const float* __restrict__ norm_scale,
    const float* __restrict__ gate_w, const float* __restrict__ gate_b,
    float* __restrict__ out)
{
    int s   = blockIdx.x;
    int tid = threadIdx.x;
    int lane = tid & 31, warp = tid >> 5;

    __shared__ float sh_t[H_DIM];
    __shared__ float sh_red[8];
    __shared__ float sh_g[E_NUM];

    float ss = 0.f;
    for (int c = tid; c < H_DIM; c += 256) {
        float v = x[s * H_DIM + c];
        sh_t[c] = v;
        out[s * H_DIM + c] = v;          // residual
        ss += v * v;
    }
    #pragma unroll
    for (int o = 16; o; o >>= 1) ss += __shfl_xor_sync(0xffffffffu, ss, o);
    if (lane == 0) sh_red[warp] = ss;
    __syncthreads();
    if (tid < 8) {
        float v = sh_red[tid];
        #pragma unroll
        for (int o = 4; o; o >>= 1) v += __shfl_xor_sync(0xffu, v, o);
        if (tid == 0) sh_red[0] = v;
    }
    __syncthreads();
    float rms = rsqrtf(sh_red[0] / (float)H_DIM + EPS);

    for (int c = tid; c < H_DIM; c += 256) {
        float tv = sh_t[c] * rms * norm_scale[c];
        sh_t[c] = tv;
        g_t[s][c] = tv;
    }
    __syncthreads();

    #pragma unroll
    for (int q = 0; q < 4; q++) {
        int e = warp * 4 + q;
        const float* gwr = gate_w + (size_t)e * H_DIM;
        float acc = 0.f;
        for (int c = lane; c < H_DIM; c += 32) acc += sh_t[c] * gwr[c];
        #pragma unroll
        for (int o = 16; o; o >>= 1) acc += __shfl_xor_sync(0xffffffffu, acc, o);
        if (lane == 0) sh_g[e] = acc + gate_b[e];
    }
    __syncthreads();

    if (tid == 0) {
        bool used[E_NUM];
        #pragma unroll
        for (int e = 0; e < E_NUM; e++) used[e] = false;
        float vals[K_TOP]; int idx[K_TOP];
        for (int k = 0; k < K_TOP; k++) {
            float best = -1e30f; int bi = 0;
            for (int e = 0; e < E_NUM; e++)
                if (!used[e] && sh_g[e] > best) { best = sh_g[e]; bi = e; }
            used[bi] = true; vals[k] = best; idx[k] = bi;
        }
        float m = vals[0], sum = 0.f, w[K_TOP];
        for (int k = 0; k < K_TOP; k++) { w[k] = __expf(vals[k] - m); sum += w[k]; }
        for (int k = 0; k < K_TOP; k++) {
            g_topk_idx[s][k] = idx[k];
            g_topk_w[s][k]   = w[k] / sum;
        }
    }
}

// ======================================================================
// Kernel 2: group (token,k) pairs by expert
// ======================================================================
__global__ void k_group()
{
    if (blockIdx.x == 0 && threadIdx.x == 0) {
        int cnt[E_NUM];
        #pragma unroll
        for (int e = 0; e < E_NUM; e++) cnt[e] = 0;
        for (int s = 0; s < S_TOK; s++)
            for (int k = 0; k < K_TOP; k++) {
                int e = g_topk_idx[s][k];
                int slot = cnt[e]++;
                g_tok[e][slot] = s;
                g_ew[e][slot]  = g_topk_w[s][k];
            }
        for (int e = 0; e < E_NUM; e++) g_cnt[e] = cnt[e];
    }
}

// ----------------------------------------------------------------------
// Shared compute helper: dot of one register-held weight row-pair against
// np4 SMEM tokens; reduces across lanes; leaves sums in a0/a1 on lane j.
// ----------------------------------------------------------------------
__device__ __forceinline__ void pair_dot_reduce(
    const float4 wa[6], const float4 wb[6],
    const float (*sh)[H_DIM], int j0, int lane,
    float a0[4], float a1[4])
{
    #pragma unroll
    for (int j = 0; j < 4; j++) { a0[j] = 0.f; a1[j] = 0.f; }
    #pragma unroll
    for (int u = 0; u < 6; u++) {
        #pragma unroll
        for (int j = 0; j < 4; j++) {
            float4 tv = *(const float4*)&sh[j0 + j][(lane + 32 * u) * 4];
            a0[j] += wa[u].x*tv.x + wa[u].y*tv.y + wa[u].z*tv.z + wa[u].w*tv.w;
            a1[j] += wb[u].x*tv.x + wb[u].y*tv.y + wb[u].z*tv.z + wb[u].w*tv.w;
        }
    }
    #pragma unroll
    for (int j = 0; j < 4; j++) {
        #pragma unroll
        for (int o = 16; o; o >>= 1) {
            a0[j] += __shfl_xor_sync(0xffffffffu, a0[j], o);
            a1[j] += __shfl_xor_sync(0xffffffffu, a1[j], o);
        }
    }
}

// ======================================================================
// Kernel 3: w1 GEMV + SwiGLU. grid=(12,E), 256 thr, 64 row-pairs/block.
// 2-deep pipeline: both pairs' 12 LDG.128 each issued before computing
// the first pair, so pair-A compute hides pair-B load latency.
// ======================================================================
__global__ void __launch_bounds__(256, 2) k_w1(
    const float* __restrict__ w1, const float* __restrict__ b1)
{
    int e = blockIdx.y;
    int cnt = g_cnt[e];
    if (cnt == 0) return;

    int pairbase = blockIdx.x * 64;
    int tid = threadIdx.x, lane = tid & 31, warp = tid >> 5;

    __shared__ float sh_t[TMAX][H_DIM];

    const float* w1e = w1 + (size_t)e * TWO_I * H_DIM;
    const float* b1e = b1 + (size_t)e * TWO_I;

    for (int p0 = 0; p0 < cnt; p0 += TMAX) {
        int np  = min(TMAX, cnt - p0);
        int np4 = (np + 3) & ~3;               // 4 or 8
        __syncthreads();
        for (int idx = tid; idx < np4 * H_DIM; idx += 256) {
            int j = idx / H_DIM, c = idx - j * H_DIM;
            sh_t[j][c] = (j < np) ? g_t[g_tok[e][p0 + j]][c] : 0.f;
        }
        __syncthreads();

        for (int p = warp; p < 64; p += 16) {
            int prA = pairbase + p;
            int prB = pairbase + p + 8;
            const float4* w0A = (const float4*)(w1e + (size_t)(2 * prA)     * H_DIM);
            const float4* w1A = (const float4*)(w1e + (size_t)(2 * prA + 1) * H_DIM);
            const float4* w0B = (const float4*)(w1e + (size_t)(2 * prB)     * H_DIM);
            const float4* w1B = (const float4*)(w1e + (size_t)(2 * prB + 1) * H_DIM);

            float4 waA[6], wbA[6], waB[6], wbB[6];
            #pragma unroll
            for (int u = 0; u < 6; u++) { waA[u] = w0A[lane + 32*u]; wbA[u] = w1A[lane + 32*u]; }
            #pragma unroll
            for (int u = 0; u < 6; u++) { waB[u] = w0B[lane + 32*u]; wbB[u] = w1B[lane + 32*u]; }

            float bgA = b1e[2*prA], blA = b1e[2*prA + 1];
            float bgB = b1e[2*prB], blB = b1e[2*prB + 1];

            for (int j0 = 0; j0 < np4; j0 += 4) {
                float a0[4], a1[4];
                pair_dot_reduce(waA, wbA, sh_t, j0, lane, a0, a1);
                #pragma unroll
                for (int j = 0; j < 4; j++) {
                    if (lane == j && j0 + j < np) {
                        float hg = fminf(a0[j] + bgA, LIMIT);
                        float hl = fminf(fmaxf(a1[j] + blA, -LIMIT), LIMIT);
                        float sg = 1.f / (1.f + __expf(-ALPHA * hg));
                        g_act[e][p0 + j0 + j][prA] = hg * sg * (hl + 1.f);
                    }
                }
            }
            for (int j0 = 0; j0 < np4; j0 += 4) {
                float a0[4], a1[4];
                pair_dot_reduce(waB, wbB, sh_t, j0, lane, a0, a1);
                #pragma unroll
                for (int j = 0; j < 4; j++) {
                    if (lane == j && j0 + j < np) {
                        float hg = fminf(a0[j] + bgB, LIMIT);
                        float hl = fminf(fmaxf(a1[j] + blB, -LIMIT), LIMIT);
                        float sg = 1.f / (1.f + __expf(-ALPHA * hg));
                        g_act[e][p0 + j0 + j][prB] = hg * sg * (hl + 1.f);
                    }
                }
            }
        }
    }
}

// ======================================================================
// Kernel 4: w2 GEMV + weighted atomic accumulate. grid=(12,E), 256 thr,
// 32 row-pairs/block, same 2-deep pipeline.
// ======================================================================
__global__ void __launch_bounds__(256, 2) k_w2(
    const float* __restrict__ w2, const float* __restrict__ b2,
    float* __restrict__ out)
{
    int e = blockIdx.y;
    int cnt = g_cnt[e];
    if (cnt == 0) return;

    int pairbase = blockIdx.x * 32;
    int tid = threadIdx.x, lane = tid & 31, warp = tid >> 5;

    __shared__ float sh_a[TMAX][I_DIM];
    __shared__ float sh_w[TMAX];
    __shared__ int   sh_tok[TMAX];

    const float* w2e = w2 + (size_t)e * H_DIM * I_DIM;
    const float* b2e = b2 + (size_t)e * H_DIM;

    for (int p0 = 0; p0 < cnt; p0 += TMAX) {
        int np  = min(TMAX, cnt - p0);
        int np4 = (np + 3) & ~3;
        __syncthreads();
        for (int idx = tid; idx < np4 * I_DIM; idx += 256) {
            int j = idx / I_DIM, c = idx - j * I_DIM;
            sh_a[j][c] = (j < np) ? g_act[e][p0 + j][c] : 0.f;
        }
        if (tid < np) {
            sh_w[tid]   = g_ew[e][p0 + tid];
            sh_tok[tid] = g_tok[e][p0 + tid];
        }
        __syncthreads();

        for (int p = warp; p < 32; p += 16) {
            int prA = pairbase + p;
            int prB = pairbase + p + 8;
            const float4* w0A = (const float4*)(w2e + (size_t)(2 * prA)     * I_DIM);
            const float4* w1A = (const float4*)(w2e + (size_t)(2 * prA + 1) * I_DIM);
            const float4* w0B = (const float4*)(w2e + (size_t)(2 * prB)     * I_DIM);
            const float4* w1B = (const float4*)(w2e + (size_t)(2 * prB + 1) * I_DIM);

            float4 waA[6], wbA[6], waB[6], wbB[6];
            #pragma unroll
            for (int u = 0; u < 6; u++) { waA[u] = w0A[lane + 32*u]; wbA[u] = w1A[lane + 32*u]; }
            #pragma unroll
            for (int u = 0; u < 6; u++) { waB[u] = w0B[lane + 32*u]; wbB[u] = w1B[lane + 32*u]; }

            float b0A = b2e[2*prA], b1A_ = b2e[2*prA + 1];
            float b0B = b2e[2*prB], b1B_ = b2e[2*prB + 1];

            for (int j0 = 0; j0 < np4; j0 += 4) {
                float a0[4], a1[4];
                pair_dot_reduce(waA, wbA, sh_a, j0, lane, a0, a1);
                #pragma unroll
                for (int j = 0; j < 4; j++) {
                    if (lane == j && j0 + j < np) {
                        float ww = sh_w[j0 + j];
                        int   tk = sh_tok[j0 + j];
                        atomicAdd(&out[(size_t)tk * H_DIM + 2*prA],     (a0[j] + b0A)  * ww);
                        atomicAdd(&out[(size_t)tk * H_DIM + 2*prA + 1], (a1[j] + b1A_) * ww);
                    }
                }
            }
            for (int j0 = 0; j0 < np4; j0 += 4) {
                float a0[4], a1[4];
                pair_dot_reduce(waB, wbB, sh_a, j0, lane, a0, a1);
                #pragma unroll
                for (int j = 0; j < 4; j++) {
                    if (lane == j && j0 + j < np) {
                        float ww = sh_w[j0 + j];
                        int   tk = sh_tok[j0 + j];
                        atomicAdd(&out[(size_t)tk * H_DIM + 2*prB],     (a0[j] + b0B)  * ww);
                        atomicAdd(&out[(size_t)tk * H_DIM + 2*prB + 1], (a1[j] + b1B_) * ww);
                    }
                }
            }
        }
    }
}

// ======================================================================
extern "C" void kernel_launch(void* const* d_in, const int* in_sizes, int n_in,
                              void* d_out, int out_size)
{
    const float* x          = (const float*)d_in[0];
    const float* norm_scale = (const float*)d_in[1];
    const float* gate_w     = (const float*)d_in[2];
    const float* gate_b     = (const float*)d_in[3];
    const float* w1         = (const float*)d_in[4];
    const float* b1         = (const float*)d_in[5];
    const float* w2         = (const float*)d_in[6];
    const float* b2         = (const float*)d_in[7];
    float* out              = (float*)d_out;

    k_route<<<S_TOK, 256>>>(x, norm_scale, gate_w, gate_b, out);
    k_group<<<1, 32>>>();
    k_w1<<<dim3(12, E_NUM), 256>>>(w1, b1);
    k_w2<<<dim3(12, E_NUM), 256>>>(w2, b2, out);
}

// round 9
// speedup vs baseline: 1.0538x; 1.0538x over previous
#include <cuda_runtime.h>
#include <math.h>
#include <stdint.h>

#define S_TOK 32
#define H_DIM 768
#define I_DIM 768
#define E_NUM 32
#define K_TOP 4
#define TWO_I 1536
#define LIMIT 7.0f
#define ALPHA 1.702f
#define EPS 1e-5f
#define TMAX 8

#define TR 32                 // weight rows per stage
#define ROW_PAD 772           // padded floats per SMEM row (conflict-free)
#define ROW_BYTES 3072        // 768 * 4
#define DSMEM_FLOATS (2 * TR * ROW_PAD + TMAX * H_DIM)
#define DSMEM_BYTES  (DSMEM_FLOATS * 4)   // 222,208

// -------- device scratch --------
__device__ float g_t[S_TOK][H_DIM];
__device__ int   g_topk_idx[S_TOK][K_TOP];
__device__ float g_topk_w[S_TOK][K_TOP];
__device__ float g_act[E_NUM][S_TOK][I_DIM];

// -------- PTX helpers --------
__device__ __forceinline__ uint32_t smem_u32(const void* p) {
    return (uint32_t)__cvta_generic_to_shared(p);
}
__device__ __forceinline__ void mbar_init(uint32_t a, uint32_t c) {
    asm volatile("mbarrier.init.shared.b64 [%0], %1;" :: "r"(a), "r"(c) : "memory");
}
__device__ __forceinline__ void mbar_expect(uint32_t a, uint32_t bytes) {
    asm volatile("mbarrier.arrive.expect_tx.shared.b64 _, [%0], %1;"
                 :: "r"(a), "r"(bytes) : "memory");
}
__device__ __forceinline__ void bulk_g2s(uint32_t dst, const void* src,
                                         uint32_t bytes, uint32_t mbar) {
    asm volatile(
        "cp.async.bulk.shared::cluster.global.mbarrier::complete_tx::bytes "
        "[%0], [%1], %2, [%3];"
        :: "r"(dst), "l"(src), "r"(bytes), "r"(mbar) : "memory");
}
__device__ __forceinline__ void mbar_wait(uint32_t mbar, uint32_t phase) {
    asm volatile(
        "{\n\t"
        ".reg .pred P;\n\t"
        "WAIT_%=:\n\t"
        "mbarrier.try_wait.parity.acquire.cta.shared::cta.b64 P, [%0], %1, 0x989680;\n\t"
        "@P bra DONE_%=;\n\t"
        "bra WAIT_%=;\n\t"
        "DONE_%=:\n\t"
        "}"
        :: "r"(mbar), "r"(phase) : "memory");
}

// ======================================================================
// Kernel 1: RMSNorm + residual init + router logits + top-4 + softmax
// ======================================================================
__global__ void __launch_bounds__(256) k_route(
    const float* __restrict__ x, const float* __restrict__ norm_scale,
    const float* __restrict__ gate_w, const float* __restrict__ gate_b,
    float* __restrict__ out)
{
    int s   = blockIdx.x;
    int tid = threadIdx.x;
    int lane = tid & 31, warp = tid >> 5;

    __shared__ float sh_t[H_DIM];
    __shared__ float sh_red[8];
    __shared__ float sh_g[E_NUM];

    float ss = 0.f;
    for (int c = tid; c < H_DIM; c += 256) {
        float v = x[s * H_DIM + c];
        sh_t[c] = v;
        out[s * H_DIM + c] = v;          // residual
        ss += v * v;
    }
    #pragma unroll
    for (int o = 16; o; o >>= 1) ss += __shfl_xor_sync(0xffffffffu, ss, o);
    if (lane == 0) sh_red[warp] = ss;
    __syncthreads();
    if (tid < 8) {
        float v = sh_red[tid];
        #pragma unroll
        for (int o = 4; o; o >>= 1) v += __shfl_xor_sync(0xffu, v, o);
        if (tid == 0) sh_red[0] = v;
    }
    __syncthreads();
    float rms = rsqrtf(sh_red[0] / (float)H_DIM + EPS);

    for (int c = tid; c < H_DIM; c += 256) {
        float tv = sh_t[c] * rms * norm_scale[c];
        sh_t[c] = tv;
        g_t[s][c] = tv;
    }
    __syncthreads();

    #pragma unroll
    for (int q = 0; q < 4; q++) {
        int e = warp * 4 + q;
        const float* gwr = gate_w + (size_t)e * H_DIM;
        float acc = 0.f;
        for (int c = lane; c < H_DIM; c += 32) acc += sh_t[c] * gwr[c];
        #pragma unroll
        for (int o = 16; o; o >>= 1) acc += __shfl_xor_sync(0xffffffffu, acc, o);
        if (lane == 0) sh_g[e] = acc + gate_b[e];
    }
    __syncthreads();

    if (tid == 0) {
        bool used[E_NUM];
        #pragma unroll
        for (int e = 0; e < E_NUM; e++) used[e] = false;
        float vals[K_TOP]; int idx[K_TOP];
        for (int k = 0; k < K_TOP; k++) {
            float best = -1e30f; int bi = 0;
            for (int e = 0; e < E_NUM; e++)
                if (!used[e] && sh_g[e] > best) { best = sh_g[e]; bi = e; }
            used[bi] = true; vals[k] = best; idx[k] = bi;
        }
        float m = vals[0], sum = 0.f, w[K_TOP];
        for (int k = 0; k < K_TOP; k++) { w[k] = __expf(vals[k] - m); sum += w[k]; }
        for (int k = 0; k < K_TOP; k++) {
            g_topk_idx[s][k] = idx[k];
            g_topk_w[s][k]   = w[k] / sum;
        }
    }
}

// ----------------------------------------------------------------------
// Per-block grouping: collect this expert's (token, weight) list in SMEM.
// ----------------------------------------------------------------------
__device__ __forceinline__ int block_group(int e, int* sh_tok, float* sh_ew) {
    int c = 0;
    for (int s = 0; s < S_TOK; s++)
        #pragma unroll
        for (int k = 0; k < K_TOP; k++)
            if (g_topk_idx[s][k] == e) {
                sh_tok[c] = s; sh_ew[c] = g_topk_w[s][k]; c++;
            }
    return c;
}

// ======================================================================
// Kernel 2: w1 GEMV + SwiGLU via bulk-async staged weights.
// grid = (12, E), 256 thr. Block covers 128 rows = 4 stages of 32.
// lane = row within stage; 8 warps split the 192 float4 columns (24 each);
// partial sums reduced through SMEM; SwiGLU epilogue writes g_act.
// ======================================================================
__global__ void __launch_bounds__(256, 1) k_w1(
    const float* __restrict__ w1, const float* __restrict__ b1)
{
    extern __shared__ float dsm[];
    float* bufs = dsm;                           // 2 * TR * ROW_PAD
    float* sh_t = dsm + 2 * TR * ROW_PAD;        // TMAX * H_DIM

    __shared__ float sh_part[8][TR][4];
    __shared__ float sh_h[TR][4];
    __shared__ int   sh_tok[S_TOK];
    __shared__ float sh_ew[S_TOK];
    __shared__ int   sh_cnt;
    __shared__ uint64_t mbar_s[2];

    int e = blockIdx.y;
    int tid = threadIdx.x, lane = tid & 31, warp = tid >> 5;

    if (tid == 0) {
        sh_cnt = block_group(e, sh_tok, sh_ew);
        mbar_init(smem_u32(&mbar_s[0]), 1);
        mbar_init(smem_u32(&mbar_s[1]), 1);
    }
    __syncthreads();
    int cnt = sh_cnt;
    if (cnt == 0) return;

    int rowbase = blockIdx.x * 128;
    const float* w1e = w1 + (size_t)e * TWO_I * H_DIM;
    const float* b1e = b1 + (size_t)e * TWO_I;
    uint32_t mb0 = smem_u32(&mbar_s[0]);
    uint32_t mb1 = smem_u32(&mbar_s[1]);
    uint32_t ph0 = 0, ph1 = 0;
    uint32_t buf_addr0 = smem_u32(bufs);
    uint32_t buf_addr1 = smem_u32(bufs + TR * ROW_PAD);

    for (int p0 = 0; p0 < cnt; p0 += TMAX) {
        int np  = min(TMAX, cnt - p0);
        int np4 = (np + 3) & ~3;
        __syncthreads();
        for (int idx = tid; idx < np4 * H_DIM; idx += 256) {
            int j = idx / H_DIM, c = idx - j * H_DIM;
            sh_t[j * H_DIM + c] = (j < np) ? g_t[sh_tok[p0 + j]][c] : 0.f;
        }
        __syncthreads();

        // prologue: stage 0 into buf0
        if (tid == 0) {
            mbar_expect(mb0, TR * ROW_BYTES);
            for (int r = 0; r < TR; r++)
                bulk_g2s(buf_addr0 + r * (ROW_PAD * 4),
                         w1e + (size_t)(rowbase + r) * H_DIM, ROW_BYTES, mb0);
        }

        for (int s = 0; s < 4; s++) {
            int b = s & 1;
            // prefetch next stage into the other buffer
            if (s + 1 < 4 && tid == 0) {
                uint32_t nmb = (b == 0) ? mb1 : mb0;
                uint32_t nba = (b == 0) ? buf_addr1 : buf_addr0;
                mbar_expect(nmb, TR * ROW_BYTES);
                for (int r = 0; r < TR; r++)
                    bulk_g2s(nba + r * (ROW_PAD * 4),
                             w1e + (size_t)(rowbase + (s + 1) * TR + r) * H_DIM,
                             ROW_BYTES, nmb);
            }
            if (b == 0) { mbar_wait(mb0, ph0); if (tid == 0) {} ph0 ^= 1; }
            else        { mbar_wait(mb1, ph1); ph1 ^= 1; }

            int glob_r0 = rowbase + s * TR;
            const float* wbuf = bufs + (size_t)b * TR * ROW_PAD;
            const float4* wrow = (const float4*)(wbuf + lane * ROW_PAD);

            for (int j0 = 0; j0 < np4; j0 += 4) {
                float a0 = 0.f, a1 = 0.f, a2 = 0.f, a3 = 0.f;
                const float* t0 = sh_t + (j0 + 0) * H_DIM;
                const float* t1 = sh_t + (j0 + 1) * H_DIM;
                const float* t2 = sh_t + (j0 + 2) * H_DIM;
                const float* t3 = sh_t + (j0 + 3) * H_DIM;
                #pragma unroll 6
                for (int i = 0; i < 24; i++) {
                    int c4 = warp * 24 + i;
                    float4 w  = wrow[c4];
                    float4 v0 = *(const float4*)&t0[c4 * 4];
                    float4 v1 = *(const float4*)&t1[c4 * 4];
                    float4 v2 = *(const float4*)&t2[c4 * 4];
                    float4 v3 = *(const float4*)&t3[c4 * 4];
                    a0 += w.x*v0.x + w.y*v0.y + w.z*v0.z + w.w*v0.w;
                    a1 += w.x*v1.x + w.y*v1.y + w.z*v1.z + w.w*v1.w;
                    a2 += w.x*v2.x + w.y*v2.y + w.z*v2.z + w.w*v2.w;
                    a3 += w.x*v3.x + w.y*v3.y + w.z*v3.z + w.w*v3.w;
                }
                sh_part[warp][lane][0] = a0;
                sh_part[warp][lane][1] = a1;
                sh_part[warp][lane][2] = a2;
                sh_part[warp][lane][3] = a3;
                __syncthreads();
                if (tid < 128) {
                    int row = tid >> 2, tk = tid & 3;
                    float h = 0.f;
                    #pragma unroll
                    for (int w8 = 0; w8 < 8; w8++) h += sh_part[w8][row][tk];
                    sh_h[row][tk] = h + b1e[glob_r0 + row];
                }
                __syncthreads();
                if (tid < 64) {
                    int m = tid >> 2, tk = tid & 3;
                    if (j0 + tk < np) {
                        float hg = fminf(sh_h[2*m][tk], LIMIT);
                        float hl = fminf(fmaxf(sh_h[2*m + 1][tk], -LIMIT), LIMIT);
                        float sg = 1.f / (1.f + __expf(-ALPHA * hg));
                        int pr = (glob_r0 >> 1) + m;
                        g_act[e][p0 + j0 + tk][pr] = hg * sg * (hl + 1.f);
                    }
                }
                __syncthreads();
            }
        }
    }
}

// ======================================================================
// Kernel 3: w2 GEMV + weighted atomic accumulate, same staging scheme.
// grid = (12, E), 256 thr. Block covers 64 rows = 2 stages of 32.
// ======================================================================
__global__ void __launch_bounds__(256, 1) k_w2(
    const float* __restrict__ w2, const float* __restrict__ b2,
    float* __restrict__ out)
{
    extern __shared__ float dsm[];
    float* bufs = dsm;
    float* sh_a = dsm + 2 * TR * ROW_PAD;

    __shared__ float sh_part[8][TR][4];
    __shared__ int   sh_tok[S_TOK];
    __shared__ float sh_ew[S_TOK];
    __shared__ int   sh_cnt;
    __shared__ uint64_t mbar_s[2];

    int e = blockIdx.y;
    int tid = threadIdx.x, lane = tid & 31, warp = tid >> 5;

    if (tid == 0) {
        sh_cnt = block_group(e, sh_tok, sh_ew);
        mbar_init(smem_u32(&mbar_s[0]), 1);
        mbar_init(smem_u32(&mbar_s[1]), 1);
    }
    __syncthreads();
    int cnt = sh_cnt;
    if (cnt == 0) return;

    int rowbase = blockIdx.x * 64;
    const float* w2e = w2 + (size_t)e * H_DIM * I_DIM;
    const float* b2e = b2 + (size_t)e * H_DIM;
    uint32_t mb0 = smem_u32(&mbar_s[0]);
    uint32_t mb1 = smem_u32(&mbar_s[1]);
    uint32_t ph0 = 0, ph1 = 0;
    uint32_t buf_addr0 = smem_u32(bufs);
    uint32_t buf_addr1 = smem_u32(bufs + TR * ROW_PAD);

    for (int p0 = 0; p0 < cnt; p0 += TMAX) {
        int np  = min(TMAX, cnt - p0);
        int np4 = (np + 3) & ~3;
        __syncthreads();
        for (int idx = tid; idx < np4 * I_DIM; idx += 256) {
            int j = idx / I_DIM, c = idx - j * I_DIM;
            sh_a[j * I_DIM + c] = (j < np) ? g_act[e][p0 + j][c] : 0.f;
        }
        __syncthreads();

        if (tid == 0) {
            mbar_expect(mb0, TR * ROW_BYTES);
            for (int r = 0; r < TR; r++)
                bulk_g2s(buf_addr0 + r * (ROW_PAD * 4),
                         w2e + (size_t)(rowbase + r) * I_DIM, ROW_BYTES, mb0);
        }

        for (int s = 0; s < 2; s++) {
            int b = s & 1;
            if (s + 1 < 2 && tid == 0) {
                mbar_expect(mb1, TR * ROW_BYTES);
                for (int r = 0; r < TR; r++)
                    bulk_g2s(buf_addr1 + r * (ROW_PAD * 4),
                             w2e + (size_t)(rowbase + TR + r) * I_DIM,
                             ROW_BYTES, mb1);
            }
            if (b == 0) { mbar_wait(mb0, ph0); ph0 ^= 1; }
            else        { mbar_wait(mb1, ph1); ph1 ^= 1; }

            int glob_r0 = rowbase + s * TR;
            const float* wbuf = bufs + (size_t)b * TR * ROW_PAD;
            const float4* wrow = (const float4*)(wbuf + lane * ROW_PAD);

            for (int j0 = 0; j0 < np4; j0 += 4) {
                float a0 = 0.f, a1 = 0.f, a2 = 0.f, a3 = 0.f;
                const float* t0 = sh_a + (j0 + 0) * I_DIM;
                const float* t1 = sh_a + (j0 + 1) * I_DIM;
                const float* t2 = sh_a + (j0 + 2) * I_DIM;
                const float* t3 = sh_a + (j0 + 3) * I_DIM;
                #pragma unroll 6
                for (int i = 0; i < 24; i++) {
                    int c4 = warp * 24 + i;
                    float4 w  = wrow[c4];
                    float4 v0 = *(const float4*)&t0[c4 * 4];
                    float4 v1 = *(const float4*)&t1[c4 * 4];
                    float4 v2 = *(const float4*)&t2[c4 * 4];
                    float4 v3 = *(const float4*)&t3[c4 * 4];
                    a0 += w.x*v0.x + w.y*v0.y + w.z*v0.z + w.w*v0.w;
                    a1 += w.x*v1.x + w.y*v1.y + w.z*v1.z + w.w*v1.w;
                    a2 += w.x*v2.x + w.y*v2.y + w.z*v2.z + w.w*v2.w;
                    a3 += w.x*v3.x + w.y*v3.y + w.z*v3.z + w.w*v3.w;
                }
                sh_part[warp][lane][0] = a0;
                sh_part[warp][lane][1] = a1;
                sh_part[warp][lane][2] = a2;
                sh_part[warp][lane][3] = a3;
                __syncthreads();
                if (tid < 128) {
                    int row = tid >> 2, tk = tid & 3;
                    if (j0 + tk < np) {
                        float h = 0.f;
                        #pragma unroll
                        for (int w8 = 0; w8 < 8; w8++) h += sh_part[w8][row][tk];
                        h += b2e[glob_r0 + row];
                        int tok = sh_tok[p0 + j0 + tk];
                        atomicAdd(&out[(size_t)tok * H_DIM + glob_r0 + row],
                                  h * sh_ew[p0 + j0 + tk]);
                    }
                }
                __syncthreads();
            }
        }
    }
}

// ======================================================================
extern "C" void kernel_launch(void* const* d_in, const int* in_sizes, int n_in,
                              void* d_out, int out_size)
{
    const float* x          = (const float*)d_in[0];
    const float* norm_scale = (const float*)d_in[1];
    const float* gate_w     = (const float*)d_in[2];
    const float* gate_b     = (const float*)d_in[3];
    const float* w1         = (const float*)d_in[4];
    const float* b1         = (const float*)d_in[5];
    const float* w2         = (const float*)d_in[6];
    const float* b2         = (const float*)d_in[7];
    float* out              = (float*)d_out;

    cudaFuncSetAttribute(k_w1, cudaFuncAttributeMaxDynamicSharedMemorySize, DSMEM_BYTES);
    cudaFuncSetAttribute(k_w2, cudaFuncAttributeMaxDynamicSharedMemorySize, DSMEM_BYTES);

    k_route<<<S_TOK, 256>>>(x, norm_scale, gate_w, gate_b, out);
    k_w1<<<dim3(12, E_NUM), 256, DSMEM_BYTES>>>(w1, b1);
    k_w2<<<dim3(12, E_NUM), 256, DSMEM_BYTES>>>(w2, b2, out);
}